// round 3
// baseline (speedup 1.0000x reference)
#include <cuda_runtime.h>
#include <math.h>

#define B_  1024
#define L_  50
#define D_  4
#define H_  512
#define T_  30
#define N4H 2048   // 4*H

// ---------------- persistent device state (allocation-free scratch) ----------------
__device__ __align__(16) float g_hA[B_ * H_];
__device__ __align__(16) float g_hB[B_ * H_];
__device__ __align__(16) float g_c[B_ * H_];
__device__ __align__(16) float g_gates[B_ * N4H];
__device__ __align__(16) float g_enc[B_ * L_ * H_];    // encoder outputs (B, L, H) ~100MB
__device__ __align__(16) float g_attn[B_ * H_];
__device__ __align__(16) float g_comb[B_ * H_];
__device__ __align__(16) float g_xA[B_ * D_];
__device__ __align__(16) float g_xB[B_ * D_];

// ---------------- init: zero h0/c0, load decoder input x0 = input[:, L-1, :] -------
__global__ void init_kernel(const float* __restrict__ input) {
    int idx = blockIdx.x * blockDim.x + threadIdx.x;
    if (idx < B_ * H_) { g_hA[idx] = 0.f; g_c[idx] = 0.f; }
    if (idx < B_ * D_) {
        int b = idx >> 2, d = idx & 3;
        g_xA[idx] = input[b * (L_ * D_) + (L_ - 1) * D_ + d];
    }
}

// ---------------- fused GEMM: C = A0@W0^T + A1@W1^T + Asm@Wsm^T + b0 + b1 ----------
// A row-major (B x K, lda = K for big operands), W row-major (N x K) at row stride ldw.
// Asm is the K=4 "small" operand (row stride ldasm). 64x64 tile, 256 threads,
// K-chunk 16, smem stored K-major so the inner loop is 2x LDS.128 + 16 FMA per k.
__global__ void __launch_bounds__(256)
gemm_kernel(const float* __restrict__ A0, const float* __restrict__ W0, int K0, int ldw0,
            const float* __restrict__ A1, const float* __restrict__ W1, int K1, int ldw1,
            const float* __restrict__ Asm, int ldasm,
            const float* __restrict__ Wsm, int ldwsm,
            const float* __restrict__ bias0, const float* __restrict__ bias1,
            float* __restrict__ C, int ldc, int do_relu)
{
    __shared__ __align__(16) float As[16][68];
    __shared__ __align__(16) float Ws[16][68];
    __shared__ float A1s[64][4];
    __shared__ float W1s[64][4];

    const int tid = threadIdx.x;
    const int tx = tid & 15;        // 16 column groups (4 cols each)
    const int ty = tid >> 4;        // 16 row groups (4 rows each)
    const int bn = blockIdx.x * 64;
    const int bm = blockIdx.y * 64;

    float acc[4][4];
    #pragma unroll
    for (int c = 0; c < 4; c++) {
        int cn = bn + tx * 4 + c;
        float bv = (bias0 ? bias0[cn] : 0.f) + (bias1 ? bias1[cn] : 0.f);
        #pragma unroll
        for (int r = 0; r < 4; r++) acc[r][c] = bv;
    }

    // stage the tiny K=4 operand (exactly 256 elements each)
    if (Asm) {
        int row = tid >> 2, k = tid & 3;
        A1s[row][k] = Asm[(bm + row) * ldasm + k];
        W1s[row][k] = Wsm[(bn + row) * ldwsm + k];
    }

    const int arow = tid >> 2;      // 0..63
    const int kg   = tid & 3;       // 0..3 -> k-subgroup of 4

    #pragma unroll 1
    for (int pass = 0; pass < 2; pass++) {
        const float* A = pass ? A1 : A0;
        const float* W = pass ? W1 : W0;
        const int    K = pass ? K1 : K0;
        const int  ldw = pass ? ldw1 : ldw0;
        if (!A) continue;

        for (int k0 = 0; k0 < K; k0 += 16) {
            float4 av = *reinterpret_cast<const float4*>(&A[(bm + arow) * K + k0 + kg * 4]);
            float4 wv = *reinterpret_cast<const float4*>(&W[(bn + arow) * ldw + k0 + kg * 4]);
            __syncthreads();
            As[kg * 4 + 0][arow] = av.x;
            As[kg * 4 + 1][arow] = av.y;
            As[kg * 4 + 2][arow] = av.z;
            As[kg * 4 + 3][arow] = av.w;
            Ws[kg * 4 + 0][arow] = wv.x;
            Ws[kg * 4 + 1][arow] = wv.y;
            Ws[kg * 4 + 2][arow] = wv.z;
            Ws[kg * 4 + 3][arow] = wv.w;
            __syncthreads();
            #pragma unroll
            for (int kk = 0; kk < 16; kk++) {
                float4 a = *reinterpret_cast<const float4*>(&As[kk][ty * 4]);
                float4 w = *reinterpret_cast<const float4*>(&Ws[kk][tx * 4]);
                float ar[4] = {a.x, a.y, a.z, a.w};
                float wr[4] = {w.x, w.y, w.z, w.w};
                #pragma unroll
                for (int r = 0; r < 4; r++)
                    #pragma unroll
                    for (int c = 0; c < 4; c++)
                        acc[r][c] += ar[r] * wr[c];
            }
        }
    }

    if (Asm) {
        #pragma unroll
        for (int r = 0; r < 4; r++)
            #pragma unroll
            for (int c = 0; c < 4; c++) {
                float s = acc[r][c];
                #pragma unroll
                for (int k = 0; k < 4; k++)
                    s += A1s[ty * 4 + r][k] * W1s[tx * 4 + c][k];
                acc[r][c] = s;
            }
    }

    #pragma unroll
    for (int r = 0; r < 4; r++) {
        int rb = bm + ty * 4 + r;
        #pragma unroll
        for (int c = 0; c < 4; c++) {
            float v = acc[r][c];
            if (do_relu) v = fmaxf(v, 0.f);
            C[rb * ldc + bn + tx * 4 + c] = v;
        }
    }
}

// ---------------- LSTM pointwise: gates -> (h, c), optional scatter into enc -------
__global__ void lstm_pointwise_kernel(const float* __restrict__ gates,
                                      const float* __restrict__ c_in,
                                      float* __restrict__ c_out,
                                      float* __restrict__ h_out,
                                      float* __restrict__ enc_slot)
{
    int idx = blockIdx.x * blockDim.x + threadIdx.x;   // B*H threads
    int b = idx >> 9, j = idx & (H_ - 1);
    const float* g = gates + b * N4H;
    float ig = g[j];
    float fg = g[H_ + j];
    float gg = g[2 * H_ + j];
    float og = g[3 * H_ + j];
    float si = 1.f / (1.f + __expf(-ig));
    float sf = 1.f / (1.f + __expf(-fg));
    float so = 1.f / (1.f + __expf(-og));
    float cn = sf * c_in[idx] + si * tanhf(gg);
    float hn = so * tanhf(cn);
    c_out[idx] = cn;
    h_out[idx] = hn;
    if (enc_slot) enc_slot[b * (L_ * H_) + j] = hn;
}

// ---------------- attention: logits -> softmax -> weighted sum of enc outputs -----
// Replicates h_r = h.reshape(H,-1).T : h_r[b,k] = h[2k + (b>=512), b & 511]
__global__ void __launch_bounds__(256)
attn_kernel(const float* __restrict__ x, const float* __restrict__ h,
            const float* __restrict__ attn_W, const float* __restrict__ attn_b,
            const float* __restrict__ enc, float* __restrict__ out)
{
    __shared__ float v[H_ + D_];
    __shared__ float wts[64];
    const int b = blockIdx.x;
    const int tid = threadIdx.x;

    if (tid < D_) v[tid] = x[b * D_ + tid];
    {
        int brow = b >> 9, bcol = b & 511;
        for (int k = tid; k < H_; k += 256)
            v[D_ + k] = h[(2 * k + brow) * H_ + bcol];
    }
    __syncthreads();

    const int warp = tid >> 5, lane = tid & 31;
    for (int l = warp; l < L_; l += 8) {
        const float* wrow = attn_W + l * (H_ + D_);
        float s = 0.f;
        for (int k = lane; k < H_ + D_; k += 32) s += v[k] * wrow[k];
        #pragma unroll
        for (int off = 16; off; off >>= 1) s += __shfl_xor_sync(0xffffffffu, s, off);
        if (lane == 0) wts[l] = s + attn_b[l];
    }
    __syncthreads();

    if (tid < 32) {
        float v1 = (tid < L_) ? wts[tid] : -1e30f;
        float v2 = (tid + 32 < L_) ? wts[tid + 32] : -1e30f;
        float m = fmaxf(v1, v2);
        #pragma unroll
        for (int off = 16; off; off >>= 1) m = fmaxf(m, __shfl_xor_sync(0xffffffffu, m, off));
        float e1 = (tid < L_) ? __expf(v1 - m) : 0.f;
        float e2 = (tid + 32 < L_) ? __expf(v2 - m) : 0.f;
        float s = e1 + e2;
        #pragma unroll
        for (int off = 16; off; off >>= 1) s += __shfl_xor_sync(0xffffffffu, s, off);
        float inv = 1.f / s;
        if (tid < L_) wts[tid] = e1 * inv;
        if (tid + 32 < L_) wts[tid + 32] = e2 * inv;
    }
    __syncthreads();

    const float* e = enc + b * (L_ * H_);
    for (int j = tid; j < H_; j += 256) {
        float s = 0.f;
        #pragma unroll
        for (int l = 0; l < L_; l++) s += wts[l] * e[l * H_ + j];
        out[b * H_ + j] = s;
    }
}

// ---------------- pred: pred = h @ out_W^T + out_b ; also next decoder input -------
__global__ void pred_kernel(const float* __restrict__ h, const float* __restrict__ out_W,
                            const float* __restrict__ out_b, float* __restrict__ out,
                            int t, float* __restrict__ x_next)
{
    const int b = blockIdx.x;
    const int warp = threadIdx.x >> 5, lane = threadIdx.x & 31;   // 4 warps = 4 outputs
    const float* hr = h + b * H_;
    const float* w = out_W + warp * H_;
    float s = 0.f;
    #pragma unroll
    for (int k = lane; k < H_; k += 32) s += hr[k] * w[k];
    #pragma unroll
    for (int off = 16; off; off >>= 1) s += __shfl_xor_sync(0xffffffffu, s, off);
    if (lane == 0) {
        float p = s + out_b[warp];
        out[(b * T_ + t) * D_ + warp] = p;
        x_next[b * D_ + warp] = p;
    }
}

// ------------------------------------- launch -------------------------------------
extern "C" void kernel_launch(void* const* d_in, const int* in_sizes, int n_in,
                              void* d_out, int out_size)
{
    // target_len may or may not be materialized as an input buffer; detect by size.
    int base = (n_in >= 16 && in_sizes[1] == 1) ? 2 : 1;

    const float* input    = (const float*)d_in[0];
    const float* enc_W_ih = (const float*)d_in[base + 0];
    const float* enc_W_hh = (const float*)d_in[base + 1];
    const float* enc_b_ih = (const float*)d_in[base + 2];
    const float* enc_b_hh = (const float*)d_in[base + 3];
    const float* attn_W   = (const float*)d_in[base + 4];
    const float* attn_b   = (const float*)d_in[base + 5];
    const float* comb_W   = (const float*)d_in[base + 6];
    const float* comb_b   = (const float*)d_in[base + 7];
    const float* dec_W_ih = (const float*)d_in[base + 8];
    const float* dec_W_hh = (const float*)d_in[base + 9];
    const float* dec_b_ih = (const float*)d_in[base + 10];
    const float* dec_b_hh = (const float*)d_in[base + 11];
    const float* out_W    = (const float*)d_in[base + 12];
    const float* out_b    = (const float*)d_in[base + 13];
    float* outp = (float*)d_out;

    float *hA, *hB, *c, *gates, *enc, *attn, *comb, *xA, *xB;
    cudaGetSymbolAddress((void**)&hA, g_hA);
    cudaGetSymbolAddress((void**)&hB, g_hB);
    cudaGetSymbolAddress((void**)&c, g_c);
    cudaGetSymbolAddress((void**)&gates, g_gates);
    cudaGetSymbolAddress((void**)&enc, g_enc);
    cudaGetSymbolAddress((void**)&attn, g_attn);
    cudaGetSymbolAddress((void**)&comb, g_comb);
    cudaGetSymbolAddress((void**)&xA, g_xA);
    cudaGetSymbolAddress((void**)&xB, g_xB);

    init_kernel<<<(B_ * H_ + 255) / 256, 256>>>(input);

    const dim3 gemm_blk(256);
    const dim3 grid_gates(N4H / 64, B_ / 64);
    const dim3 grid_comb(H_ / 64, B_ / 64);

    // ---------------- encoder ----------------
    float* h_in = hA;
    float* h_out = hB;
    for (int t = 0; t < L_; t++) {
        gemm_kernel<<<grid_gates, gemm_blk>>>(
            h_in, enc_W_hh, H_, H_,
            nullptr, nullptr, 0, 0,
            input + t * D_, L_ * D_, enc_W_ih, D_,
            enc_b_ih, enc_b_hh,
            gates, N4H, 0);
        lstm_pointwise_kernel<<<B_ * H_ / 256, 256>>>(gates, c, c, h_out, enc + t * H_);
        float* tmp = h_in; h_in = h_out; h_out = tmp;
    }

    // ---------------- decoder ----------------
    float* x_in = xA;
    float* x_out = xB;
    for (int t = 0; t < T_; t++) {
        attn_kernel<<<B_, 256>>>(x_in, h_in, attn_W, attn_b, enc, attn);
        // comb = relu([x, attn] @ comb_W^T + comb_b); comb_W is (H, H+D), x hits cols [0,4)
        gemm_kernel<<<grid_comb, gemm_blk>>>(
            attn, comb_W + D_, H_, H_ + D_,
            nullptr, nullptr, 0, 0,
            x_in, D_, comb_W, H_ + D_,
            comb_b, nullptr,
            comb, H_, 1);
        // gates = comb @ dec_W_ih^T + h @ dec_W_hh^T + b_ih + b_hh
        gemm_kernel<<<grid_gates, gemm_blk>>>(
            comb, dec_W_ih, H_, H_,
            h_in, dec_W_hh, H_, H_,
            nullptr, 0, nullptr, 0,
            dec_b_ih, dec_b_hh,
            gates, N4H, 0);
        lstm_pointwise_kernel<<<B_ * H_ / 256, 256>>>(gates, c, c, h_out, nullptr);
        pred_kernel<<<B_, 128>>>(h_out, out_W, out_b, outp, t, x_out);
        float* tmp = h_in; h_in = h_out; h_out = tmp;
        float* tx = x_in; x_in = x_out; x_out = tx;
    }
}